// round 12
// baseline (speedup 1.0000x reference)
#include <cuda_runtime.h>
#include <math.h>

// ---------------------------------------------------------------------------
// EASeq2SeqLSTM: B=256, L=365, F=32, S=27, H=256, HOR=24, NT=1
//
// Persistent single-kernel, 128 CTAs (1/SM), split arrive/wait grid barrier
// (replay-safe: epochs relative to per-launch g_gen snapshot).
// CTA tile: 32(batch) x 64(gate-cols), gate cols packed col = hidx*4+gate.
// R11: 256 threads (8 warps, 2/SMSP), 2x4 outputs/thread. Per-k per-warp smem
// traffic: one B LDS.128 sweep (2 wf) + one broadcast A LDS.64 (1 wf) -> 24
// wf/k SM-wide, below the 32-cyc FFMA floor; 2 warps/SMSP hide LDS latency.
// ---------------------------------------------------------------------------

#define LSEQ  365
#define BATCH 256
#define FDIM  32
#define SDIM  27
#define HDIM  256
#define HORZ  24
#define NBLK  128
#define NTHR  256
#define GSTRIDE (NBLK * NTHR)

// dynamic smem: B persist (768 rows x 64 cols) + A double buffer (2 x 32x34)
#define SBP_FLOATS (768 * 64)            // 49152
#define SA_FLOATS  (2 * 1088)            // 2176
#define SMEM_BYTES ((SBP_FLOATS + SA_FLOATS) * 4)   // 205312 B

// ------------------------- device scratch (static) -------------------------
__device__ float g_easeq[(size_t)LSEQ * BATCH * HDIM];   // 95.6 MB
__device__ float g_h0[BATCH * HDIM];
__device__ float g_h1[BATCH * HDIM];
__device__ float g_hc0[BATCH * 512];    // decoder concat(hA, hB) ping
__device__ float g_hc1[BATCH * 512];    // decoder concat(hA, hB) pong
__device__ float g_si[BATCH * HDIM];
__device__ float g_sg[BATCH * HDIM];
__device__ __align__(16) float g_Bea [288 * 1024];  // EA packed [K][col], K: x(32) then h(256)
__device__ __align__(16) float g_Benc[512 * 1024];  // enc packed: ea(256) then h(256)
__device__ __align__(16) float g_Bd0 [256 * 1024];  // dec layer0 (Whh)
__device__ __align__(16) float g_Bd1 [512 * 1024];  // dec layer1: hA(256) then hB(256)
__device__ __align__(16) float g_bEA [1024];
__device__ __align__(16) float g_bENC[1024];
__device__ __align__(16) float g_bD0 [1024];
__device__ __align__(16) float g_bD1 [1024];
__device__ __align__(16) float g_w0  [1024];        // dec_Wih0 packed
__device__ float g_din[BATCH];
__device__ unsigned int g_count = 0;
__device__ unsigned int g_gen   = 0;

// --------------------- split grid barrier (epoch based) --------------------
// Targets are (base + ep); base snapshotted at kernel entry -> graph-replay
// safe regardless of g_gen's persistent value.
__device__ __forceinline__ void bar_arrive()
{
    __threadfence();
    __syncthreads();
    if (threadIdx.x == 0) {
        if (atomicAdd(&g_count, 1u) == NBLK - 1u) {
            atomicExch(&g_count, 0u);
            __threadfence();
            atomicAdd(&g_gen, 1u);
        }
    }
}
__device__ __forceinline__ void bar_wait(unsigned int target)
{
    if (threadIdx.x == 0) {
        while ((int)(*((volatile unsigned int*)&g_gen) - target) < 0) { }
        __threadfence();
    }
    __syncthreads();
}

// ------------------------------ fast math ----------------------------------
__device__ __forceinline__ float sigm(float v)
{
    return __fdividef(1.0f, 1.0f + __expf(-v));
}
__device__ __forceinline__ float tanh_f(float v)
{
    float x = fminf(fmaxf(v, -10.0f), 10.0f);
    float t = __expf(2.0f * x);
    return __fdividef(t - 1.0f, t + 1.0f);
}

// ------------------------------- GEMM tile ---------------------------------
// acc[8] = acc[r*4+c]: 2 batch rows (rg*2+r) x 4 gate-cols (cg*4+c).
// Per k: one broadcast LDS.64 of A (2 rows, k-major sA[k*34+row]) + one
// LDS.128 of B. A staged per 32-k block (4 floats/thread), double-buffered.
// B persisted in smem: Bp[k*64 + c], absolute kb = kb0+kb.
template <class AF>
__device__ __forceinline__ void gemm_run(float (&acc)[8], int kb0, int nkb,
                                         AF Aload, const float* __restrict__ Bp,
                                         float* sA, int tid)
{
    const int lk  = tid & 31;            // loader: k within block
    const int lr0 = (tid >> 5) << 2;     // loader: first of 4 rows
    const int cg  = tid & 15;            // col group (4 cols)
    const int rg  = tid >> 4;            // row group (2 rows)
    float ra[4];

#pragma unroll
    for (int p = 0; p < 4; p++) ra[p] = Aload(kb0 * 32 + lk, lr0 + p);
    int buf = 0;
#pragma unroll
    for (int p = 0; p < 4; p++) sA[lk * 34 + lr0 + p] = ra[p];
    __syncthreads();

    for (int kb = 0; kb < nkb; kb++) {
        const bool more = (kb + 1 < nkb);
        if (more) {
#pragma unroll
            for (int p = 0; p < 4; p++)
                ra[p] = Aload((kb0 + kb + 1) * 32 + lk, lr0 + p);
        }
        const float* A_ = sA + buf * 1088 + rg * 2;
        const float* B_ = Bp + (kb0 + kb) * 2048 + cg * 4;
#pragma unroll
        for (int kk = 0; kk < 32; kk++) {
            float2 a = *(const float2*)(A_ + kk * 34);
            float4 b = *(const float4*)(B_ + kk * 64);
            acc[0] += a.x * b.x; acc[1] += a.x * b.y;
            acc[2] += a.x * b.z; acc[3] += a.x * b.w;
            acc[4] += a.y * b.x; acc[5] += a.y * b.y;
            acc[6] += a.y * b.z; acc[7] += a.y * b.w;
        }
        if (more) {
            float* An = sA + (buf ^ 1) * 1088;
#pragma unroll
            for (int p = 0; p < 4; p++) An[lk * 34 + lr0 + p] = ra[p];
        }
        __syncthreads();
        buf ^= 1;
    }
}

// --------------------------------- kernel ----------------------------------
__global__ void __launch_bounds__(NTHR, 1)
ea_seq2seq_kernel(const float* __restrict__ x,    const float* __restrict__ s,
                  const float* __restrict__ Wf,   const float* __restrict__ bf,
                  const float* __restrict__ Wo,   const float* __restrict__ bo,
                  const float* __restrict__ Wi,   const float* __restrict__ bi,
                  const float* __restrict__ Wg,   const float* __restrict__ bg,
                  const float* __restrict__ Wsi,  const float* __restrict__ bsi,
                  const float* __restrict__ Wsg,  const float* __restrict__ bsg,
                  const float* __restrict__ eWih, const float* __restrict__ eWhh,
                  const float* __restrict__ ebih, const float* __restrict__ ebhh,
                  const float* __restrict__ dWih0,const float* __restrict__ dWhh0,
                  const float* __restrict__ dbih0,const float* __restrict__ dbhh0,
                  const float* __restrict__ dWih1,const float* __restrict__ dWhh1,
                  const float* __restrict__ dbih1,const float* __restrict__ dbhh1,
                  const float* __restrict__ fcW,  const float* __restrict__ fcb,
                  float* __restrict__ out)
{
    extern __shared__ __align__(16) float smem[];
    float* sBp = smem;                    // [768][64] phase-dependent B slice
    float* sA  = smem + SBP_FLOATS;       // 2 x 1088 A stage buffers
    __shared__ float sred[8];

    const int tid  = threadIdx.x;
    const int bid  = blockIdx.x;
    const int gtid = bid * NTHR + tid;
    const int rt   = bid >> 4, ct = bid & 15;
    const int r0   = rt * 32;                // batch rows [r0, r0+32)
    const int cg   = tid & 15;               // col group
    const int rg   = tid >> 4;               // row group (0..15)
    const int row0 = r0 + rg * 2;            // first of 2 global batch rows
    const int hidx = ct * 16 + cg;           // hidden unit owned
    const int col0 = ct * 64 + cg * 4;       // packed gate-col base

    // Per-launch barrier base: snapshot BEFORE this CTA's first arrive; g_gen
    // can only advance after all CTAs arrive once -> race-free, replay-safe.
    const unsigned int base = *((volatile unsigned int*)&g_gen);
    unsigned int ep = 0;

    // ---------------- prep: pack weights, biases, si/sg, zero h ------------
    // EA: col = h*4 + g (g: 0=f,1=o,2=i,3=g). K order = [x(32), h(256)] which
    // matches W's concat([x,h]) layout -> identity copy of W rows.
    for (int i = gtid; i < 288 * 1024; i += GSTRIDE) {
        int k = i >> 10, col = i & 1023, h = col >> 2, g = col & 3;
        const float* W = (g == 0) ? Wf : (g == 1) ? Wo : (g == 2) ? Wi : Wg;
        g_Bea[i] = W[h * 288 + k];
    }
    // enc: torch gate order i,f,g,o; K: [0,256) = Wih (ea_seq), [256,512) = Whh
    for (int i = gtid; i < 512 * 1024; i += GSTRIDE) {
        int k = i >> 10, col = i & 1023, n = (col & 3) * 256 + (col >> 2);
        g_Benc[i] = (k < 256) ? eWih[n * 256 + k] : eWhh[n * 256 + (k - 256)];
    }
    for (int i = gtid; i < 256 * 1024; i += GSTRIDE) {
        int k = i >> 10, col = i & 1023, n = (col & 3) * 256 + (col >> 2);
        g_Bd0[i] = dWhh0[n * 256 + k];
    }
    for (int i = gtid; i < 512 * 1024; i += GSTRIDE) {
        int k = i >> 10, col = i & 1023, n = (col & 3) * 256 + (col >> 2);
        g_Bd1[i] = (k < 256) ? dWih1[n * 256 + k] : dWhh1[n * 256 + (k - 256)];
    }
    for (int i = gtid; i < 1024; i += GSTRIDE) {
        int h = i >> 2, g = i & 3, n = g * 256 + h;
        g_bEA[i]  = ((g == 0) ? bf : (g == 1) ? bo : (g == 2) ? bi : bg)[h];
        g_bENC[i] = ebih[n] + ebhh[n];
        g_bD0[i]  = dbih0[n] + dbhh0[n];
        g_bD1[i]  = dbih1[n] + dbhh1[n];
        g_w0[i]   = dWih0[n];
    }
    for (int i = gtid; i < BATCH * HDIM; i += GSTRIDE) {
        int b = i >> 8, h = i & 255;
        float as = bsi[h], ag = bsg[h];
#pragma unroll
        for (int j = 0; j < SDIM; j++) {
            float sv = s[b * SDIM + j];
            as += sv * Wsi[h * SDIM + j];
            ag += sv * Wsg[h * SDIM + j];
        }
        g_si[i] = as; g_sg[i] = ag;
        g_h0[i] = 0.0f;
    }
    bar_arrive(); ep++;
    bar_wait(base + ep);   // prep fully visible

    // ---------------- phase 1: EA (365 steps, K = 32(x) + 256(h)) ----------
    for (int i = tid; i < 288 * 64; i += NTHR)
        sBp[i] = g_Bea[(i >> 6) * 1024 + ct * 64 + (i & 63)];
    const float4 bEAv = *(const float4*)&g_bEA[col0];
    float sival[2], sgval[2], cS[2];
#pragma unroll
    for (int r = 0; r < 2; r++) {
        sival[r] = g_si[(row0 + r) * 256 + hidx];
        sgval[r] = g_sg[(row0 + r) * 256 + hidx];
        cS[r] = 0.0f;
    }

    float* hin  = g_h0;
    float* hout = g_h1;
    for (int t = 0; t < LSEQ; t++) {
        float acc[8];
#pragma unroll
        for (int r = 0; r < 2; r++) {
            acc[r * 4 + 0] = bEAv.x; acc[r * 4 + 1] = bEAv.y;
            acc[r * 4 + 2] = bEAv.z; acc[r * 4 + 3] = bEAv.w;
        }
        auto ldX = [&](int kg, int rr) -> float {
            return x[((r0 + rr) * LSEQ + t) * FDIM + kg];
        };
        gemm_run(acc, 0, 1, ldX, sBp, sA, tid);     // x-part (hides barrier)
        if (t > 0) bar_wait(base + ep);             // h^{t-1} ready
        auto ldH = [&](int kg, int rr) -> float {
            return hin[(r0 + rr) * 256 + (kg - 32)];
        };
        gemm_run(acc, 1, 8, ldH, sBp, sA, tid);     // h-part
#pragma unroll
        for (int r = 0; r < 2; r++) {
            float f = sigm(acc[r * 4 + 0]), o = sigm(acc[r * 4 + 1]);
            float ii = sigm(acc[r * 4 + 2] + sival[r]);
            float gg = tanh_f(acc[r * 4 + 3] + sgval[r]);
            float c = f * cS[r] + ii * gg;
            float h = o * tanh_f(c);
            cS[r] = c;
            int idx = (row0 + r) * 256 + hidx;
            hout[idx] = h;
            g_easeq[(size_t)t * (BATCH * HDIM) + idx] = h;
        }
        bar_arrive(); ep++;
        float* tp = hin; hin = hout; hout = tp;
    }

    // ---------------- phase 2: encoder (365 steps, K = 256 + 256) ----------
    // ea_seq fully written -> input half runs BEFORE the wait (barrier hidden).
    for (int i = tid; i < 512 * 64; i += NTHR)
        sBp[i] = g_Benc[(i >> 6) * 1024 + ct * 64 + (i & 63)];
    const float4 bEv = *(const float4*)&g_bENC[col0];

    for (int t = 0; t < LSEQ; t++) {
        float acc[8];
#pragma unroll
        for (int r = 0; r < 2; r++) {
            acc[r * 4 + 0] = bEv.x; acc[r * 4 + 1] = bEv.y;
            acc[r * 4 + 2] = bEv.z; acc[r * 4 + 3] = bEv.w;
        }
        auto ldE = [&](int kg, int rr) -> float {
            return g_easeq[(size_t)t * (BATCH * HDIM) + (r0 + rr) * 256 + kg];
        };
        gemm_run(acc, 0, 8, ldE, sBp, sA, tid);     // ea half (hides barrier)
        bar_wait(base + ep);                        // h^{t-1} ready
        auto ldH = [&](int kg, int rr) -> float {
            return hin[(r0 + rr) * 256 + (kg - 256)];
        };
        gemm_run(acc, 8, 8, ldH, sBp, sA, tid);     // h half
#pragma unroll
        for (int r = 0; r < 2; r++) {
            float ii = sigm(acc[r * 4 + 0]), f = sigm(acc[r * 4 + 1]);
            float gg = tanh_f(acc[r * 4 + 2]), o = sigm(acc[r * 4 + 3]);
            float c = f * cS[r] + ii * gg;
            float h = o * tanh_f(c);
            cS[r] = c;
            hout[(row0 + r) * 256 + hidx] = h;
        }
        bar_arrive(); ep++;
        float* tp = hin; hin = hout; hout = tp;
    }

    // ---------------- decoder init: hA=hB=h_enc; cA=cB=c_enc ---------------
    for (int i = tid; i < 256 * 64; i += NTHR)
        sBp[i] = g_Bd0[(i >> 6) * 1024 + ct * 64 + (i & 63)];
    for (int i = tid; i < 512 * 64; i += NTHR)
        sBp[16384 + i] = g_Bd1[(i >> 6) * 1024 + ct * 64 + (i & 63)];
    const float4 bD0v = *(const float4*)&g_bD0[col0];
    const float4 w0v  = *(const float4*)&g_w0[col0];
    const float4 bD1v = *(const float4*)&g_bD1[col0];
    float cA[2], cB[2];
#pragma unroll
    for (int r = 0; r < 2; r++) { cA[r] = cS[r]; cB[r] = cS[r]; }

    bar_wait(base + ep);                            // h_enc ready
    for (int i = gtid; i < BATCH * HDIM; i += GSTRIDE) {
        float hv = hin[i];
        int b = i >> 8, h = i & 255;
        g_hc0[b * 512 + h]       = hv;   // hA
        g_hc0[b * 512 + 256 + h] = hv;   // hB
    }
    if (gtid < BATCH) g_din[gtid] = 0.0f;
    bar_arrive(); ep++;

    float* hcin  = g_hc0;
    float* hcout = g_hc1;

    // ---------------- decoder loop (24 steps) ------------------------------
    for (int st = 0; st < HORZ; st++) {
        // layer 0: input = din scalar + hA (K=256)
        bar_wait(base + ep);                        // hcin + din ready
        {
            float acc[8];
#pragma unroll
            for (int r = 0; r < 2; r++) {
                float d = g_din[row0 + r];
                acc[r * 4 + 0] = bD0v.x + d * w0v.x;
                acc[r * 4 + 1] = bD0v.y + d * w0v.y;
                acc[r * 4 + 2] = bD0v.z + d * w0v.z;
                acc[r * 4 + 3] = bD0v.w + d * w0v.w;
            }
            auto ldA0 = [&](int kg, int rr) -> float {
                return hcin[(r0 + rr) * 512 + kg];
            };
            gemm_run(acc, 0, 8, ldA0, sBp, sA, tid);
#pragma unroll
            for (int r = 0; r < 2; r++) {
                float ii = sigm(acc[r * 4 + 0]), f = sigm(acc[r * 4 + 1]);
                float gg = tanh_f(acc[r * 4 + 2]), o = sigm(acc[r * 4 + 3]);
                float c = f * cA[r] + ii * gg;
                float h = o * tanh_f(c);
                cA[r] = c;
                hcout[(row0 + r) * 512 + hidx] = h;  // hA (new)
            }
        }
        bar_arrive(); ep++;
        // layer 1: hB half first (no dep on layer-0 barrier), then hA half
        {
            float acc[8];
#pragma unroll
            for (int r = 0; r < 2; r++) {
                acc[r * 4 + 0] = bD1v.x; acc[r * 4 + 1] = bD1v.y;
                acc[r * 4 + 2] = bD1v.z; acc[r * 4 + 3] = bD1v.w;
            }
            auto ldB = [&](int kg, int rr) -> float {
                return hcin[(r0 + rr) * 512 + kg];  // kg in [256,512) = hB old
            };
            gemm_run(acc, 8, 8, ldB, sBp + 16384, sA, tid);
            bar_wait(base + ep);                    // hA(new) ready
            auto ldAn = [&](int kg, int rr) -> float {
                return hcout[(r0 + rr) * 512 + kg]; // hA new
            };
            gemm_run(acc, 0, 8, ldAn, sBp + 16384, sA, tid);
#pragma unroll
            for (int r = 0; r < 2; r++) {
                float ii = sigm(acc[r * 4 + 0]), f = sigm(acc[r * 4 + 1]);
                float gg = tanh_f(acc[r * 4 + 2]), o = sigm(acc[r * 4 + 3]);
                float c = f * cB[r] + ii * gg;
                float h = o * tanh_f(c);
                cB[r] = c;
                hcout[(row0 + r) * 512 + 256 + hidx] = h;  // hB (new)
            }
        }
        bar_arrive(); ep++;
        // pred: out[b, st] = hB . fcW + fcb ; feeds din for next step.
        bar_wait(base + ep);
        {
            int bl = tid >> 7, kk = tid & 127;      // 2 batch rows per CTA
            const float* hb = hcout + (bid * 2 + bl) * 512 + 256;
            float v = hb[kk] * fcW[kk] + hb[128 + kk] * fcW[128 + kk];
#pragma unroll
            for (int off = 16; off > 0; off >>= 1)
                v += __shfl_down_sync(0xffffffffu, v, off);
            if ((tid & 31) == 0) sred[tid >> 5] = v;
            __syncthreads();
            if (tid < 2) {
                float p = sred[tid * 4] + sred[tid * 4 + 1] +
                          sred[tid * 4 + 2] + sred[tid * 4 + 3] + fcb[0];
                int b2 = bid * 2 + tid;
                out[b2 * HORZ + st] = p;
                g_din[b2] = p;
            }
        }
        bar_arrive(); ep++;
        float* tp = hcin; hcin = hcout; hcout = tp;
    }
}

// ------------------------------ launch shim --------------------------------
extern "C" void kernel_launch(void* const* d_in, const int* in_sizes, int n_in,
                              void* d_out, int out_size)
{
    (void)in_sizes; (void)n_in; (void)out_size;
    cudaFuncSetAttribute(ea_seq2seq_kernel,
                         cudaFuncAttributeMaxDynamicSharedMemorySize, SMEM_BYTES);
    const float* p[28];
    for (int i = 0; i < 28; i++) p[i] = (const float*)d_in[i];
    ea_seq2seq_kernel<<<NBLK, NTHR, SMEM_BYTES>>>(
        p[0], p[1], p[2], p[3], p[4], p[5], p[6], p[7], p[8], p[9],
        p[10], p[11], p[12], p[13], p[14], p[15], p[16], p[17],
        p[18], p[19], p[20], p[21], p[22], p[23], p[24], p[25],
        p[26], p[27], (float*)d_out);
}

// round 17
// speedup vs baseline: 1.2649x; 1.2649x over previous
#include <cuda_runtime.h>
#include <math.h>

// ---------------------------------------------------------------------------
// EASeq2SeqLSTM: B=256, L=365, F=32, S=27, H=256, HOR=24, NT=1
//
// Persistent single-kernel, 128 CTAs (1/SM), split arrive/wait grid barrier
// (replay-safe: epochs relative to per-launch g_gen snapshot).
// CTA tile: 32(batch) x 64(gate-cols), gate cols packed col = hidx*4+gate.
// R12: 256 threads = two warpsets; both keep R7's 4x4 thread tile, but split
// each 32-k block in half (kk 0..15 vs 16..31). 2 warps/SMSP hide LDS latency
// with unchanged FFMA-pipe work and unchanged crossbar traffic. Warpset 1
// publishes register partials through smem once per step (cheap reduction).
// ---------------------------------------------------------------------------

#define LSEQ  365
#define BATCH 256
#define FDIM  32
#define SDIM  27
#define HDIM  256
#define HORZ  24
#define NBLK  128
#define NTHR  256
#define GSTRIDE (NBLK * NTHR)

// dynamic smem: B persist (768x64) + A double buffer (2 x 32x36) + reduction
#define SBP_FLOATS (768 * 64)            // 49152
#define SA_FLOATS  (2 * 1152)            // 2304
#define SRED_FLOATS (128 * 17)           // 2176
#define SMEM_BYTES ((SBP_FLOATS + SA_FLOATS + SRED_FLOATS) * 4)   // 214528 B

// ------------------------- device scratch (static) -------------------------
__device__ float g_easeq[(size_t)LSEQ * BATCH * HDIM];   // 95.6 MB
__device__ float g_h0[BATCH * HDIM];
__device__ float g_h1[BATCH * HDIM];
__device__ float g_hc0[BATCH * 512];    // decoder concat(hA, hB) ping
__device__ float g_hc1[BATCH * 512];    // decoder concat(hA, hB) pong
__device__ float g_si[BATCH * HDIM];
__device__ float g_sg[BATCH * HDIM];
__device__ __align__(16) float g_Bea [288 * 1024];  // EA packed [K][col], K: x(32) then h(256)
__device__ __align__(16) float g_Benc[512 * 1024];  // enc packed: ea(256) then h(256)
__device__ __align__(16) float g_Bd0 [256 * 1024];  // dec layer0 (Whh)
__device__ __align__(16) float g_Bd1 [512 * 1024];  // dec layer1: hA(256) then hB(256)
__device__ __align__(16) float g_bEA [1024];
__device__ __align__(16) float g_bENC[1024];
__device__ __align__(16) float g_bD0 [1024];
__device__ __align__(16) float g_bD1 [1024];
__device__ __align__(16) float g_w0  [1024];        // dec_Wih0 packed
__device__ float g_din[BATCH];
__device__ unsigned int g_count = 0;
__device__ unsigned int g_gen   = 0;

// --------------------- split grid barrier (epoch based) --------------------
// Targets are (base + ep); base snapshotted at kernel entry -> graph-replay
// safe regardless of g_gen's persistent value.
__device__ __forceinline__ void bar_arrive()
{
    __threadfence();
    __syncthreads();
    if (threadIdx.x == 0) {
        if (atomicAdd(&g_count, 1u) == NBLK - 1u) {
            atomicExch(&g_count, 0u);
            __threadfence();
            atomicAdd(&g_gen, 1u);
        }
    }
}
__device__ __forceinline__ void bar_wait(unsigned int target)
{
    if (threadIdx.x == 0) {
        while ((int)(*((volatile unsigned int*)&g_gen) - target) < 0) { }
        __threadfence();
    }
    __syncthreads();
}

// ------------------------------ fast math ----------------------------------
__device__ __forceinline__ float sigm(float v)
{
    return __fdividef(1.0f, 1.0f + __expf(-v));
}
__device__ __forceinline__ float tanh_f(float v)
{
    float x = fminf(fmaxf(v, -10.0f), 10.0f);
    float t = __expf(2.0f * x);
    return __fdividef(t - 1.0f, t + 1.0f);
}

// ------------------------------- GEMM tile ---------------------------------
// acc[16] = acc[r*4+c]: 4 batch rows (rg*4+r) x 4 gate-cols (cg*4+c) PARTIALS.
// Warpset (tid>>7) computes kk in [kh, kh+16) of each 32-k block; both sets
// walk the same blocks so __syncthreads stays aligned. Staging shared: 256
// threads x 4 floats. B persisted in smem: Bp[k*64+c], absolute kb = kb0+kb.
template <class AF>
__device__ __forceinline__ void gemm_run(float (&acc)[16], int kb0, int nkb,
                                         AF Aload, const float* __restrict__ Bp,
                                         float* sA, int tid)
{
    const int lk  = tid & 31;            // loader: k within block
    const int lr0 = (tid >> 5) << 2;     // loader: first of 4 rows
    const int cg  = tid & 15;            // col group (4 cols)
    const int rg  = (tid >> 4) & 7;      // row group (4 rows)
    const int kh  = (tid >> 7) << 4;     // warpset k-half offset: 0 or 16
    float ra[4];

#pragma unroll
    for (int p = 0; p < 4; p++) ra[p] = Aload(kb0 * 32 + lk, lr0 + p);
    int buf = 0;
#pragma unroll
    for (int p = 0; p < 4; p++) sA[lk * 36 + lr0 + p] = ra[p];
    __syncthreads();

    for (int kb = 0; kb < nkb; kb++) {
        const bool more = (kb + 1 < nkb);
        if (more) {
#pragma unroll
            for (int p = 0; p < 4; p++)
                ra[p] = Aload((kb0 + kb + 1) * 32 + lk, lr0 + p);
        }
        const float* A_ = sA + buf * 1152 + rg * 4 + kh * 36;
        const float* B_ = Bp + (kb0 + kb) * 2048 + cg * 4 + kh * 64;
#pragma unroll
        for (int kk = 0; kk < 16; kk++) {
            float4 a = *(const float4*)(A_ + kk * 36);
            float4 b = *(const float4*)(B_ + kk * 64);
            acc[ 0] += a.x * b.x; acc[ 1] += a.x * b.y;
            acc[ 2] += a.x * b.z; acc[ 3] += a.x * b.w;
            acc[ 4] += a.y * b.x; acc[ 5] += a.y * b.y;
            acc[ 6] += a.y * b.z; acc[ 7] += a.y * b.w;
            acc[ 8] += a.z * b.x; acc[ 9] += a.z * b.y;
            acc[10] += a.z * b.z; acc[11] += a.z * b.w;
            acc[12] += a.w * b.x; acc[13] += a.w * b.y;
            acc[14] += a.w * b.z; acc[15] += a.w * b.w;
        }
        if (more) {
            float* An = sA + (buf ^ 1) * 1152;
#pragma unroll
            for (int p = 0; p < 4; p++) An[lk * 36 + lr0 + p] = ra[p];
        }
        __syncthreads();
        buf ^= 1;
    }
}

// Combine warpset partials: set1 publishes, set0 adds. Caller (set0) then does
// the activation. Safe to reuse sRed every step: the next write happens only
// after bar_arrive's __syncthreads orders it behind this step's reads.
__device__ __forceinline__ void reduce_halves(float (&acc)[16], float* sRed,
                                              int tid)
{
    if (tid >= 128) {
        float* dst = sRed + (tid - 128) * 17;
#pragma unroll
        for (int j = 0; j < 16; j++) dst[j] = acc[j];
    }
    __syncthreads();
    if (tid < 128) {
        const float* src = sRed + tid * 17;
#pragma unroll
        for (int j = 0; j < 16; j++) acc[j] += src[j];
    }
}

// --------------------------------- kernel ----------------------------------
__global__ void __launch_bounds__(NTHR, 1)
ea_seq2seq_kernel(const float* __restrict__ x,    const float* __restrict__ s,
                  const float* __restrict__ Wf,   const float* __restrict__ bf,
                  const float* __restrict__ Wo,   const float* __restrict__ bo,
                  const float* __restrict__ Wi,   const float* __restrict__ bi,
                  const float* __restrict__ Wg,   const float* __restrict__ bg,
                  const float* __restrict__ Wsi,  const float* __restrict__ bsi,
                  const float* __restrict__ Wsg,  const float* __restrict__ bsg,
                  const float* __restrict__ eWih, const float* __restrict__ eWhh,
                  const float* __restrict__ ebih, const float* __restrict__ ebhh,
                  const float* __restrict__ dWih0,const float* __restrict__ dWhh0,
                  const float* __restrict__ dbih0,const float* __restrict__ dbhh0,
                  const float* __restrict__ dWih1,const float* __restrict__ dWhh1,
                  const float* __restrict__ dbih1,const float* __restrict__ dbhh1,
                  const float* __restrict__ fcW,  const float* __restrict__ fcb,
                  float* __restrict__ out)
{
    extern __shared__ __align__(16) float smem[];
    float* sBp  = smem;                       // [768][64] phase-dep B slice
    float* sA   = smem + SBP_FLOATS;          // 2 x 1152 A stage buffers
    float* sRed = smem + SBP_FLOATS + SA_FLOATS;  // 128 x 17 partials
    __shared__ float sred[8];

    const int tid  = threadIdx.x;
    const int bid  = blockIdx.x;
    const int gtid = bid * NTHR + tid;
    const int rt   = bid >> 4, ct = bid & 15;
    const int r0   = rt * 32;                // batch rows [r0, r0+32)
    const int cg   = tid & 15;               // col group
    const int rg   = (tid >> 4) & 7;         // row group (shared by both sets)
    const int row0 = r0 + rg * 4;            // first of 4 global batch rows
    const int hidx = ct * 16 + cg;           // hidden unit owned
    const int col0 = ct * 64 + cg * 4;       // packed gate-col base
    const bool act = (tid < 128);            // warpset 0 does activations

    // Per-launch barrier base: snapshot BEFORE this CTA's first arrive; g_gen
    // can only advance after all CTAs arrive once -> race-free, replay-safe.
    const unsigned int base = *((volatile unsigned int*)&g_gen);
    unsigned int ep = 0;

    // ---------------- prep: pack weights, biases, si/sg, zero h ------------
    // EA: col = h*4 + g (g: 0=f,1=o,2=i,3=g). K order = [x(32), h(256)] which
    // matches W's concat([x,h]) layout -> identity copy of W rows.
    for (int i = gtid; i < 288 * 1024; i += GSTRIDE) {
        int k = i >> 10, col = i & 1023, h = col >> 2, g = col & 3;
        const float* W = (g == 0) ? Wf : (g == 1) ? Wo : (g == 2) ? Wi : Wg;
        g_Bea[i] = W[h * 288 + k];
    }
    // enc: torch gate order i,f,g,o; K: [0,256) = Wih (ea_seq), [256,512) = Whh
    for (int i = gtid; i < 512 * 1024; i += GSTRIDE) {
        int k = i >> 10, col = i & 1023, n = (col & 3) * 256 + (col >> 2);
        g_Benc[i] = (k < 256) ? eWih[n * 256 + k] : eWhh[n * 256 + (k - 256)];
    }
    for (int i = gtid; i < 256 * 1024; i += GSTRIDE) {
        int k = i >> 10, col = i & 1023, n = (col & 3) * 256 + (col >> 2);
        g_Bd0[i] = dWhh0[n * 256 + k];
    }
    for (int i = gtid; i < 512 * 1024; i += GSTRIDE) {
        int k = i >> 10, col = i & 1023, n = (col & 3) * 256 + (col >> 2);
        g_Bd1[i] = (k < 256) ? dWih1[n * 256 + k] : dWhh1[n * 256 + (k - 256)];
    }
    for (int i = gtid; i < 1024; i += GSTRIDE) {
        int h = i >> 2, g = i & 3, n = g * 256 + h;
        g_bEA[i]  = ((g == 0) ? bf : (g == 1) ? bo : (g == 2) ? bi : bg)[h];
        g_bENC[i] = ebih[n] + ebhh[n];
        g_bD0[i]  = dbih0[n] + dbhh0[n];
        g_bD1[i]  = dbih1[n] + dbhh1[n];
        g_w0[i]   = dWih0[n];
    }
    for (int i = gtid; i < BATCH * HDIM; i += GSTRIDE) {
        int b = i >> 8, h = i & 255;
        float as = bsi[h], ag = bsg[h];
#pragma unroll
        for (int j = 0; j < SDIM; j++) {
            float sv = s[b * SDIM + j];
            as += sv * Wsi[h * SDIM + j];
            ag += sv * Wsg[h * SDIM + j];
        }
        g_si[i] = as; g_sg[i] = ag;
        g_h0[i] = 0.0f;
    }
    bar_arrive(); ep++;
    bar_wait(base + ep);   // prep fully visible

    // ---------------- phase 1: EA (365 steps, K = 32(x) + 256(h)) ----------
    for (int i = tid; i < 288 * 64; i += NTHR)
        sBp[i] = g_Bea[(i >> 6) * 1024 + ct * 64 + (i & 63)];
    const float4 bEAv = *(const float4*)&g_bEA[col0];
    float sival[4], sgval[4], cS[4];
#pragma unroll
    for (int r = 0; r < 4; r++) {
        sival[r] = g_si[(row0 + r) * 256 + hidx];
        sgval[r] = g_sg[(row0 + r) * 256 + hidx];
        cS[r] = 0.0f;
    }

    float* hin  = g_h0;
    float* hout = g_h1;
    for (int t = 0; t < LSEQ; t++) {
        float acc[16];
#pragma unroll
        for (int j = 0; j < 16; j++) acc[j] = 0.0f;
        auto ldX = [&](int kg, int rr) -> float {
            return x[((r0 + rr) * LSEQ + t) * FDIM + kg];
        };
        gemm_run(acc, 0, 1, ldX, sBp, sA, tid);     // x-part (hides barrier)
        if (t > 0) bar_wait(base + ep);             // h^{t-1} ready
        auto ldH = [&](int kg, int rr) -> float {
            return hin[(r0 + rr) * 256 + (kg - 32)];
        };
        gemm_run(acc, 1, 8, ldH, sBp, sA, tid);     // h-part
        reduce_halves(acc, sRed, tid);
        if (act) {
#pragma unroll
            for (int r = 0; r < 4; r++) {
                float f = sigm(acc[r * 4 + 0] + bEAv.x);
                float o = sigm(acc[r * 4 + 1] + bEAv.y);
                float ii = sigm(acc[r * 4 + 2] + bEAv.z + sival[r]);
                float gg = tanh_f(acc[r * 4 + 3] + bEAv.w + sgval[r]);
                float c = f * cS[r] + ii * gg;
                float h = o * tanh_f(c);
                cS[r] = c;
                int idx = (row0 + r) * 256 + hidx;
                hout[idx] = h;
                g_easeq[(size_t)t * (BATCH * HDIM) + idx] = h;
            }
        }
        bar_arrive(); ep++;
        float* tp = hin; hin = hout; hout = tp;
    }

    // ---------------- phase 2: encoder (365 steps, K = 256 + 256) ----------
    // ea_seq fully written -> input half runs BEFORE the wait (barrier hidden).
    for (int i = tid; i < 512 * 64; i += NTHR)
        sBp[i] = g_Benc[(i >> 6) * 1024 + ct * 64 + (i & 63)];
    const float4 bEv = *(const float4*)&g_bENC[col0];

    for (int t = 0; t < LSEQ; t++) {
        float acc[16];
#pragma unroll
        for (int j = 0; j < 16; j++) acc[j] = 0.0f;
        auto ldE = [&](int kg, int rr) -> float {
            return g_easeq[(size_t)t * (BATCH * HDIM) + (r0 + rr) * 256 + kg];
        };
        gemm_run(acc, 0, 8, ldE, sBp, sA, tid);     // ea half (hides barrier)
        bar_wait(base + ep);                        // h^{t-1} ready
        auto ldH = [&](int kg, int rr) -> float {
            return hin[(r0 + rr) * 256 + (kg - 256)];
        };
        gemm_run(acc, 8, 8, ldH, sBp, sA, tid);     // h half
        reduce_halves(acc, sRed, tid);
        if (act) {
#pragma unroll
            for (int r = 0; r < 4; r++) {
                float ii = sigm(acc[r * 4 + 0] + bEv.x);
                float f  = sigm(acc[r * 4 + 1] + bEv.y);
                float gg = tanh_f(acc[r * 4 + 2] + bEv.z);
                float o  = sigm(acc[r * 4 + 3] + bEv.w);
                float c = f * cS[r] + ii * gg;
                float h = o * tanh_f(c);
                cS[r] = c;
                hout[(row0 + r) * 256 + hidx] = h;
            }
        }
        bar_arrive(); ep++;
        float* tp = hin; hin = hout; hout = tp;
    }

    // ---------------- decoder init: hA=hB=h_enc; cA=cB=c_enc ---------------
    for (int i = tid; i < 256 * 64; i += NTHR)
        sBp[i] = g_Bd0[(i >> 6) * 1024 + ct * 64 + (i & 63)];
    for (int i = tid; i < 512 * 64; i += NTHR)
        sBp[16384 + i] = g_Bd1[(i >> 6) * 1024 + ct * 64 + (i & 63)];
    const float4 bD0v = *(const float4*)&g_bD0[col0];
    const float4 w0v  = *(const float4*)&g_w0[col0];
    const float4 bD1v = *(const float4*)&g_bD1[col0];
    float cA[4], cB[4];
#pragma unroll
    for (int r = 0; r < 4; r++) { cA[r] = cS[r]; cB[r] = cS[r]; }

    bar_wait(base + ep);                            // h_enc ready
    for (int i = gtid; i < BATCH * HDIM; i += GSTRIDE) {
        float hv = hin[i];
        int b = i >> 8, h = i & 255;
        g_hc0[b * 512 + h]       = hv;   // hA
        g_hc0[b * 512 + 256 + h] = hv;   // hB
    }
    if (gtid < BATCH) g_din[gtid] = 0.0f;
    bar_arrive(); ep++;

    float* hcin  = g_hc0;
    float* hcout = g_hc1;

    // ---------------- decoder loop (24 steps) ------------------------------
    for (int st = 0; st < HORZ; st++) {
        // layer 0: input = din scalar + hA (K=256)
        bar_wait(base + ep);                        // hcin + din ready
        {
            float acc[16];
#pragma unroll
            for (int j = 0; j < 16; j++) acc[j] = 0.0f;
            auto ldA0 = [&](int kg, int rr) -> float {
                return hcin[(r0 + rr) * 512 + kg];
            };
            gemm_run(acc, 0, 8, ldA0, sBp, sA, tid);
            reduce_halves(acc, sRed, tid);
            if (act) {
#pragma unroll
                for (int r = 0; r < 4; r++) {
                    float d = g_din[row0 + r];
                    float ii = sigm(acc[r * 4 + 0] + bD0v.x + d * w0v.x);
                    float f  = sigm(acc[r * 4 + 1] + bD0v.y + d * w0v.y);
                    float gg = tanh_f(acc[r * 4 + 2] + bD0v.z + d * w0v.z);
                    float o  = sigm(acc[r * 4 + 3] + bD0v.w + d * w0v.w);
                    float c = f * cA[r] + ii * gg;
                    float h = o * tanh_f(c);
                    cA[r] = c;
                    hcout[(row0 + r) * 512 + hidx] = h;  // hA (new)
                }
            }
        }
        bar_arrive(); ep++;
        // layer 1: hB half first (no dep on layer-0 barrier), then hA half
        {
            float acc[16];
#pragma unroll
            for (int j = 0; j < 16; j++) acc[j] = 0.0f;
            auto ldB = [&](int kg, int rr) -> float {
                return hcin[(r0 + rr) * 512 + kg];  // kg in [256,512) = hB old
            };
            gemm_run(acc, 8, 8, ldB, sBp + 16384, sA, tid);
            bar_wait(base + ep);                    // hA(new) ready
            auto ldAn = [&](int kg, int rr) -> float {
                return hcout[(r0 + rr) * 512 + kg]; // hA new
            };
            gemm_run(acc, 0, 8, ldAn, sBp + 16384, sA, tid);
            reduce_halves(acc, sRed, tid);
            if (act) {
#pragma unroll
                for (int r = 0; r < 4; r++) {
                    float ii = sigm(acc[r * 4 + 0] + bD1v.x);
                    float f  = sigm(acc[r * 4 + 1] + bD1v.y);
                    float gg = tanh_f(acc[r * 4 + 2] + bD1v.z);
                    float o  = sigm(acc[r * 4 + 3] + bD1v.w);
                    float c = f * cB[r] + ii * gg;
                    float h = o * tanh_f(c);
                    cB[r] = c;
                    hcout[(row0 + r) * 512 + 256 + hidx] = h;  // hB (new)
                }
            }
        }
        bar_arrive(); ep++;
        // pred: out[b, st] = hB . fcW + fcb ; feeds din for next step.
        bar_wait(base + ep);
        {
            int bl = tid >> 7, kk = tid & 127;      // 2 batch rows per CTA
            const float* hb = hcout + (bid * 2 + bl) * 512 + 256;
            float v = hb[kk] * fcW[kk] + hb[128 + kk] * fcW[128 + kk];
#pragma unroll
            for (int off = 16; off > 0; off >>= 1)
                v += __shfl_down_sync(0xffffffffu, v, off);
            if ((tid & 31) == 0) sred[tid >> 5] = v;
            __syncthreads();
            if (tid < 2) {
                float p = sred[tid * 4] + sred[tid * 4 + 1] +
                          sred[tid * 4 + 2] + sred[tid * 4 + 3] + fcb[0];
                int b2 = bid * 2 + tid;
                out[b2 * HORZ + st] = p;
                g_din[b2] = p;
            }
        }
        bar_arrive(); ep++;
        float* tp = hcin; hcin = hcout; hcout = tp;
    }
}

// ------------------------------ launch shim --------------------------------
extern "C" void kernel_launch(void* const* d_in, const int* in_sizes, int n_in,
                              void* d_out, int out_size)
{
    (void)in_sizes; (void)n_in; (void)out_size;
    cudaFuncSetAttribute(ea_seq2seq_kernel,
                         cudaFuncAttributeMaxDynamicSharedMemorySize, SMEM_BYTES);
    const float* p[28];
    for (int i = 0; i < 28; i++) p[i] = (const float*)d_in[i];
    ea_seq2seq_kernel<<<NBLK, NTHR, SMEM_BYTES>>>(
        p[0], p[1], p[2], p[3], p[4], p[5], p[6], p[7], p[8], p[9],
        p[10], p[11], p[12], p[13], p[14], p[15], p[16], p[17],
        p[18], p[19], p[20], p[21], p[22], p[23], p[24], p[25],
        p[26], p[27], (float*)d_out);
}